// round 4
// baseline (speedup 1.0000x reference)
#include <cuda_runtime.h>
#include <math.h>

#define T_STEPS 2048
#define BATCH   64
#define IDIM    256
#define HDIM    512

// ---------------------------------------------------------------------------
// Group-barrier state (4 independent batch groups, 32 blocks each).
// Zero-initialized at module load. g_cnt is reset to 0 at every barrier exit;
// g_gen is monotonically increasing (wrap-safe for ~2M launches).
// ---------------------------------------------------------------------------
__device__ unsigned int g_cnt[4];
__device__ unsigned int g_gen[4];

// ===========================================================================
// Kernel A: xproj[m][n] = sum_k x[m][k] * Wi[n][k] + bi[n] + bh[n]
//   M = T*B = 131072, N = H = 512, K = I = 256.  Written directly into d_out.
// 64x64 block tile, BK=16, 256 threads, 4x4 register tile.
// ===========================================================================
#define BM 64
#define BN 64
#define BK 16

__global__ __launch_bounds__(256, 2)
void xproj_kernel(const float* __restrict__ x,
                  const float* __restrict__ Wi,
                  const float* __restrict__ bi,
                  const float* __restrict__ bh,
                  float* __restrict__ out)
{
    __shared__ float As[BK][BM + 4];
    __shared__ float Bs[BK][BN + 4];

    const int m0 = blockIdx.y * BM;
    const int n0 = blockIdx.x * BN;
    const int tid = threadIdx.x;
    const int tx = tid & 15;   // 0..15 -> n sub-tile
    const int ty = tid >> 4;   // 0..15 -> m sub-tile

    // loader mapping: 256 threads load one float4 each per tile (64 rows x 16 k)
    const int lr = tid >> 2;          // row 0..63
    const int lc = (tid & 3) * 4;     // k   0,4,8,12

    float acc[4][4] = {};

    for (int k0 = 0; k0 < IDIM; k0 += BK) {
        float4 av = *(const float4*)&x [(size_t)(m0 + lr) * IDIM + k0 + lc];
        float4 bv = *(const float4*)&Wi[(size_t)(n0 + lr) * IDIM + k0 + lc];
        As[lc + 0][lr] = av.x; As[lc + 1][lr] = av.y;
        As[lc + 2][lr] = av.z; As[lc + 3][lr] = av.w;
        Bs[lc + 0][lr] = bv.x; Bs[lc + 1][lr] = bv.y;
        Bs[lc + 2][lr] = bv.z; Bs[lc + 3][lr] = bv.w;
        __syncthreads();

        #pragma unroll
        for (int k = 0; k < BK; k++) {
            float4 a = *(const float4*)&As[k][ty * 4];
            float4 b = *(const float4*)&Bs[k][tx * 4];
            acc[0][0] = fmaf(a.x, b.x, acc[0][0]);
            acc[0][1] = fmaf(a.x, b.y, acc[0][1]);
            acc[0][2] = fmaf(a.x, b.z, acc[0][2]);
            acc[0][3] = fmaf(a.x, b.w, acc[0][3]);
            acc[1][0] = fmaf(a.y, b.x, acc[1][0]);
            acc[1][1] = fmaf(a.y, b.y, acc[1][1]);
            acc[1][2] = fmaf(a.y, b.z, acc[1][2]);
            acc[1][3] = fmaf(a.y, b.w, acc[1][3]);
            acc[2][0] = fmaf(a.z, b.x, acc[2][0]);
            acc[2][1] = fmaf(a.z, b.y, acc[2][1]);
            acc[2][2] = fmaf(a.z, b.z, acc[2][2]);
            acc[2][3] = fmaf(a.z, b.w, acc[2][3]);
            acc[3][0] = fmaf(a.w, b.x, acc[3][0]);
            acc[3][1] = fmaf(a.w, b.y, acc[3][1]);
            acc[3][2] = fmaf(a.w, b.z, acc[3][2]);
            acc[3][3] = fmaf(a.w, b.w, acc[3][3]);
        }
        __syncthreads();
    }

    // epilogue: + bi[n] + bh[n], vectorized store (cols are 4 consecutive n)
    const int ncol = n0 + tx * 4;
    float4 bias;
    bias.x = bi[ncol + 0] + bh[ncol + 0];
    bias.y = bi[ncol + 1] + bh[ncol + 1];
    bias.z = bi[ncol + 2] + bh[ncol + 2];
    bias.w = bi[ncol + 3] + bh[ncol + 3];

    #pragma unroll
    for (int i = 0; i < 4; i++) {
        const size_t row = (size_t)(m0 + ty * 4 + i);
        float4 v;
        v.x = acc[i][0] + bias.x;
        v.y = acc[i][1] + bias.y;
        v.z = acc[i][2] + bias.z;
        v.w = acc[i][3] + bias.w;
        *(float4*)&out[row * HDIM + ncol] = v;
    }
}

// ===========================================================================
// Kernel B: persistent recurrence.
//   128 blocks = 4 batch-groups (16 batches each) x 32 j-tiles (16 cols each).
//   Wh slice (16x512) stays in smem for all 2048 steps.
//   h_prev restaged from d_out[t-1] each step; d_out[t] updated in place:
//       d_out[t] = tanh(d_out[t] + h_prev @ Wh_sliceT)
//   Only the 32 blocks of a batch-group share data -> group-local barrier.
// ===========================================================================
#define BT   16          // batch tile
#define JT   16          // hidden-col tile
#define NJB  32          // j-blocks per group (512/16)
#define HS   (HDIM + 4)  // padded smem row stride (516 floats, 16B aligned)

__device__ __forceinline__ void group_barrier(int grp)
{
    __syncthreads();
    if (threadIdx.x == 0) {
        volatile unsigned int* genp = &g_gen[grp];
        unsigned int my = *genp;
        __threadfence();                       // order prior writes + the read
        if (atomicAdd(&g_cnt[grp], 1u) == NJB - 1) {
            g_cnt[grp] = 0;                    // reset for next barrier
            __threadfence();
            atomicExch(&g_gen[grp], my + 1);   // release
        } else {
            while (*genp == my) { }            // spin on L2 line (broadcast)
        }
        __threadfence();                       // acquire-ish
    }
    __syncthreads();
}

extern __shared__ float smem_rnn[];

__global__ __launch_bounds__(256, 1)
void rnn_kernel(const float* __restrict__ Wh, float* __restrict__ out)
{
    float* Ws = smem_rnn;            // [JT][HS]
    float* hs = smem_rnn + JT * HS;  // [BT][HS]

    const int g   = blockIdx.x;
    const int grp = g >> 5;          // batch group 0..3
    const int jb  = g & 31;          // j tile 0..31
    const int b0  = grp * BT;
    const int j0  = jb * JT;
    const int tid = threadIdx.x;
    const int tx  = tid & 15;        // local j
    const int ty  = tid >> 4;        // local b

    // Load Wh slice once: Ws[j][k] = Wh[(j0+j)*512 + k]
    for (int i = tid; i < JT * (HDIM / 4); i += 256) {
        const int j = i >> 7;                 // / 128
        const int c = (i & 127) * 4;
        float4 v = *(const float4*)&Wh[(size_t)(j0 + j) * HDIM + c];
        *(float4*)&Ws[j * HS + c] = v;
    }
    __syncthreads();

    const int myb = b0 + ty;
    const int myj = j0 + tx;

    // t = 0: h0 = 0 -> h = tanh(xproj)
    {
        const size_t idx = ((size_t)myb) * HDIM + myj;
        out[idx] = tanhf(out[idx]);
    }
    __threadfence();
    group_barrier(grp);

    for (int t = 1; t < T_STEPS; t++) {
        // stage h_prev[b0..b0+15][0..511] (32 KB) into smem, coalesced
        const float* hp = out + ((size_t)(t - 1) * BATCH + b0) * HDIM;
        #pragma unroll
        for (int i = 0; i < 8; i++) {
            const int idx = tid + 256 * i;    // 0..2047 float4s
            const int r = idx >> 7;           // row 0..15
            const int c = (idx & 127) * 4;    // col
            float4 v = *(const float4*)&hp[(size_t)r * HDIM + c];
            *(float4*)&hs[r * HS + c] = v;
        }
        __syncthreads();

        // dot(h_prev[myb,:], Wh[myj,:]) with 4 accumulators for ILP
        const float* hrow = hs + ty * HS;
        const float* wrow = Ws + tx * HS;
        float a0 = 0.f, a1 = 0.f, a2 = 0.f, a3 = 0.f;
        #pragma unroll 16
        for (int k4 = 0; k4 < HDIM / 4; k4++) {
            float4 hv = *(const float4*)&hrow[k4 * 4];
            float4 wv = *(const float4*)&wrow[k4 * 4];
            a0 = fmaf(hv.x, wv.x, a0);
            a1 = fmaf(hv.y, wv.y, a1);
            a2 = fmaf(hv.z, wv.z, a2);
            a3 = fmaf(hv.w, wv.w, a3);
        }
        const float acc = (a0 + a1) + (a2 + a3);

        const size_t idx = ((size_t)t * BATCH + myb) * HDIM + myj;
        out[idx] = tanhf(out[idx] + acc);

        __threadfence();
        group_barrier(grp);   // includes the __syncthreads protecting hs reuse
    }
}

// ===========================================================================
// Kernel C: append final hidden state (== output[T-1]) after the sequence,
// only when out_size includes it.
// ===========================================================================
__global__ void copy_hidden_kernel(float* __restrict__ out)
{
    const int i = blockIdx.x * 256 + threadIdx.x;
    const size_t src = ((size_t)(T_STEPS - 1) * BATCH) * HDIM + i;
    const size_t dst = ((size_t)T_STEPS * BATCH) * HDIM + i;
    out[dst] = out[src];
}

// ===========================================================================
extern "C" void kernel_launch(void* const* d_in, const int* in_sizes, int n_in,
                              void* d_out, int out_size)
{
    const float* x  = (const float*)d_in[0];
    const float* Wi = (const float*)d_in[1];
    const float* bi = (const float*)d_in[2];
    const float* Wh = (const float*)d_in[3];
    const float* bh = (const float*)d_in[4];
    float* out = (float*)d_out;

    // 1) xproj + biases straight into d_out
    dim3 gA(HDIM / BN, (T_STEPS * BATCH) / BM);
    xproj_kernel<<<gA, 256>>>(x, Wi, bi, bh, out);

    // 2) persistent recurrence (dynamic smem: Wh slice + h stage, ~66 KB)
    const int smem_bytes = (JT * HS + BT * HS) * (int)sizeof(float);
    cudaFuncSetAttribute(rnn_kernel,
                         cudaFuncAttributeMaxDynamicSharedMemorySize,
                         smem_bytes);
    rnn_kernel<<<128, 256, smem_bytes>>>(Wh, out);

    // 3) optional final-hidden tail
    const long long full = (long long)T_STEPS * BATCH * HDIM + (long long)BATCH * HDIM;
    if ((long long)out_size >= full)
        copy_hidden_kernel<<<(BATCH * HDIM) / 256, 256>>>(out);
}

// round 5
// speedup vs baseline: 1.5702x; 1.5702x over previous
#include <cuda_runtime.h>
#include <math.h>

#define T_STEPS 2048
#define BATCH   64
#define IDIM    256
#define HDIM    512

// ---------------------------------------------------------------------------
// Group barrier state: 4 independent batch groups x 32 blocks.
// ---------------------------------------------------------------------------
#define NJB 32
__device__ unsigned int g_cnt[4];
__device__ unsigned int g_gen[4];

// ===========================================================================
// Kernel A: xproj = x @ Wi^T + bi + bh, written straight into d_out.
// M=131072, N=512, K=256. 64x64x16 tiles, 256 thr, 4x4 register tile.
// ===========================================================================
#define BM 64
#define BN 64
#define BK 16

__global__ __launch_bounds__(256, 2)
void xproj_kernel(const float* __restrict__ x,
                  const float* __restrict__ Wi,
                  const float* __restrict__ bi,
                  const float* __restrict__ bh,
                  float* __restrict__ out)
{
    __shared__ float As[BK][BM + 4];
    __shared__ float Bs[BK][BN + 4];

    const int m0 = blockIdx.y * BM;
    const int n0 = blockIdx.x * BN;
    const int tid = threadIdx.x;
    const int tx = tid & 15;
    const int ty = tid >> 4;

    const int lr = tid >> 2;
    const int lc = (tid & 3) * 4;

    float acc[4][4] = {};

    for (int k0 = 0; k0 < IDIM; k0 += BK) {
        float4 av = *(const float4*)&x [(size_t)(m0 + lr) * IDIM + k0 + lc];
        float4 bv = *(const float4*)&Wi[(size_t)(n0 + lr) * IDIM + k0 + lc];
        As[lc + 0][lr] = av.x; As[lc + 1][lr] = av.y;
        As[lc + 2][lr] = av.z; As[lc + 3][lr] = av.w;
        Bs[lc + 0][lr] = bv.x; Bs[lc + 1][lr] = bv.y;
        Bs[lc + 2][lr] = bv.z; Bs[lc + 3][lr] = bv.w;
        __syncthreads();

        #pragma unroll
        for (int k = 0; k < BK; k++) {
            float4 a = *(const float4*)&As[k][ty * 4];
            float4 b = *(const float4*)&Bs[k][tx * 4];
            acc[0][0] = fmaf(a.x, b.x, acc[0][0]);
            acc[0][1] = fmaf(a.x, b.y, acc[0][1]);
            acc[0][2] = fmaf(a.x, b.z, acc[0][2]);
            acc[0][3] = fmaf(a.x, b.w, acc[0][3]);
            acc[1][0] = fmaf(a.y, b.x, acc[1][0]);
            acc[1][1] = fmaf(a.y, b.y, acc[1][1]);
            acc[1][2] = fmaf(a.y, b.z, acc[1][2]);
            acc[1][3] = fmaf(a.y, b.w, acc[1][3]);
            acc[2][0] = fmaf(a.z, b.x, acc[2][0]);
            acc[2][1] = fmaf(a.z, b.y, acc[2][1]);
            acc[2][2] = fmaf(a.z, b.z, acc[2][2]);
            acc[2][3] = fmaf(a.z, b.w, acc[2][3]);
            acc[3][0] = fmaf(a.w, b.x, acc[3][0]);
            acc[3][1] = fmaf(a.w, b.y, acc[3][1]);
            acc[3][2] = fmaf(a.w, b.z, acc[3][2]);
            acc[3][3] = fmaf(a.w, b.w, acc[3][3]);
        }
        __syncthreads();
    }

    const int ncol = n0 + tx * 4;
    float4 bias;
    bias.x = bi[ncol + 0] + bh[ncol + 0];
    bias.y = bi[ncol + 1] + bh[ncol + 1];
    bias.z = bi[ncol + 2] + bh[ncol + 2];
    bias.w = bi[ncol + 3] + bh[ncol + 3];

    #pragma unroll
    for (int i = 0; i < 4; i++) {
        const size_t row = (size_t)(m0 + ty * 4 + i);
        float4 v;
        v.x = acc[i][0] + bias.x;
        v.y = acc[i][1] + bias.y;
        v.z = acc[i][2] + bias.z;
        v.w = acc[i][3] + bias.w;
        *(float4*)&out[row * HDIM + ncol] = v;
    }
}

// ===========================================================================
// Kernel B: persistent recurrence, weight-stationary in registers.
//   128 blocks = 4 batch groups (16 b) x 32 j-blocks (16 j).
//   256 threads = 16 j x 16 k-chunks (32 k each). Thread owns its Wh chunk
//   in registers (packed f32x2) for the entire 2048-step loop.
//   Per step: stage h_prev (32 KB) -> smem, broadcast-read h, FFMA2 dot
//   partials, smem reduce over k-chunks, tanh, store, acq/rel group barrier.
// ===========================================================================
#define BT 16
#define JT 16
#define KC 16
#define KW 32
#define HS (HDIM + 4)   // 516 floats, 16B-aligned rows
#define PS 272          // ps stride per k-chunk (mod 32 = 16: conflict-free)

__device__ __forceinline__ unsigned long long ffma2(unsigned long long a,
                                                    unsigned long long b,
                                                    unsigned long long c)
{
    unsigned long long d;
    asm("fma.rn.f32x2 %0, %1, %2, %3;" : "=l"(d) : "l"(a), "l"(b), "l"(c));
    return d;
}

__device__ __forceinline__ float f2sum(unsigned long long a)
{
    float lo, hi;
    asm("mov.b64 {%0, %1}, %2;" : "=f"(lo), "=f"(hi) : "l"(a));
    return lo + hi;
}

__device__ __forceinline__ void group_barrier(int grp)
{
    __syncthreads();
    if (threadIdx.x == 0) {
        unsigned int my;
        asm volatile("ld.acquire.gpu.global.u32 %0, [%1];"
                     : "=r"(my) : "l"(g_gen + grp));
        unsigned int old;
        asm volatile("atom.acq_rel.gpu.global.add.u32 %0, [%1], %2;"
                     : "=r"(old) : "l"(g_cnt + grp), "r"(1u));
        if (old == NJB - 1) {
            asm volatile("st.relaxed.gpu.global.u32 [%0], %1;"
                         :: "l"(g_cnt + grp), "r"(0u));
            unsigned int dump;
            asm volatile("atom.release.gpu.global.exch.b32 %0, [%1], %2;"
                         : "=r"(dump) : "l"(g_gen + grp), "r"(my + 1u));
        } else {
            unsigned int cur;
            do {
                asm volatile("ld.acquire.gpu.global.u32 %0, [%1];"
                             : "=r"(cur) : "l"(g_gen + grp));
            } while (cur == my);
        }
    }
    __syncthreads();
}

extern __shared__ float smem_rnn[];

__global__ __launch_bounds__(256, 1)
void rnn_kernel(const float* __restrict__ Wh, float* __restrict__ out)
{
    float* hs = smem_rnn;             // [BT][HS]  staged h_prev
    float* ps = smem_rnn + BT * HS;   // [KC][PS]  k-chunk partials

    const int g   = blockIdx.x;
    const int grp = g >> 5;
    const int jb  = g & 31;
    const int b0  = grp * BT;
    const int j0  = jb * JT;
    const int tid = threadIdx.x;
    const int j   = tid & 15;         // owned j column (compute phase)
    const int kc  = tid >> 4;         // owned k-chunk  (compute phase)
    const int rj  = tid & 15;         // output j       (reduce phase)
    const int rb  = tid >> 4;         // output batch   (reduce phase)

    // --- weight-stationary: Wh[j0+j][kc*32 .. +31] packed into 16 f32x2 regs
    unsigned long long w2[16];
    {
        const ulonglong2* wp =
            (const ulonglong2*)(Wh + (size_t)(j0 + j) * HDIM + kc * KW);
        #pragma unroll
        for (int i = 0; i < 8; i++) {
            ulonglong2 v = wp[i];
            w2[2 * i]     = v.x;
            w2[2 * i + 1] = v.y;
        }
    }

    // --- t = 0: h0 = 0 -> h = tanh(xproj)
    {
        const size_t idx = (size_t)(b0 + rb) * HDIM + (j0 + rj);
        out[idx] = tanhf(out[idx]);
    }
    group_barrier(grp);

    for (int t = 1; t < T_STEPS; t++) {
        // stage h_prev[b0..b0+15][:] (32 KB) into smem, coalesced
        const float* hp = out + ((size_t)(t - 1) * BATCH + b0) * HDIM;
        #pragma unroll
        for (int i = 0; i < 8; i++) {
            const int idx = tid + 256 * i;
            const int r = idx >> 7;
            const int c = (idx & 127) * 4;
            float4 v = *(const float4*)&hp[(size_t)r * HDIM + c];
            *(float4*)&hs[r * HS + c] = v;
        }
        // prefetch this thread's xproj value while staging is in flight
        const size_t oidx = ((size_t)t * BATCH + (b0 + rb)) * HDIM + (j0 + rj);
        const float xp = out[oidx];
        __syncthreads();

        // partial dots: for each batch, 32-k chunk vs register weights
        #pragma unroll
        for (int b = 0; b < BT; b++) {
            const ulonglong2* h2 =
                (const ulonglong2*)(hs + b * HS + kc * KW);
            unsigned long long a0 = 0ull, a1 = 0ull;
            #pragma unroll
            for (int i = 0; i < 4; i++) {
                ulonglong2 u = h2[2 * i];
                ulonglong2 v = h2[2 * i + 1];
                a0 = ffma2(u.x, w2[4 * i + 0], a0);
                a1 = ffma2(u.y, w2[4 * i + 1], a1);
                a0 = ffma2(v.x, w2[4 * i + 2], a0);
                a1 = ffma2(v.y, w2[4 * i + 3], a1);
            }
            ps[kc * PS + b * 16 + j] = f2sum(a0) + f2sum(a1);
        }
        __syncthreads();

        // reduce 16 k-chunk partials, activation, store
        float s = 0.f;
        #pragma unroll
        for (int k2 = 0; k2 < KC; k2++)
            s += ps[k2 * PS + rb * 16 + rj];
        out[oidx] = tanhf(xp + s);

        group_barrier(grp);   // also protects hs/ps reuse next iteration
    }
}

// ===========================================================================
// Kernel C: append final hidden state (== output[T-1]) when out_size has it.
// ===========================================================================
__global__ void copy_hidden_kernel(float* __restrict__ out)
{
    const int i = blockIdx.x * 256 + threadIdx.x;
    const size_t src = ((size_t)(T_STEPS - 1) * BATCH) * HDIM + i;
    const size_t dst = ((size_t)T_STEPS * BATCH) * HDIM + i;
    out[dst] = out[src];
}

// ===========================================================================
extern "C" void kernel_launch(void* const* d_in, const int* in_sizes, int n_in,
                              void* d_out, int out_size)
{
    const float* x  = (const float*)d_in[0];
    const float* Wi = (const float*)d_in[1];
    const float* bi = (const float*)d_in[2];
    const float* Wh = (const float*)d_in[3];
    const float* bh = (const float*)d_in[4];
    float* out = (float*)d_out;

    dim3 gA(HDIM / BN, (T_STEPS * BATCH) / BM);
    xproj_kernel<<<gA, 256>>>(x, Wi, bi, bh, out);

    const int smem_bytes = (BT * HS + KC * PS) * (int)sizeof(float);
    cudaFuncSetAttribute(rnn_kernel,
                         cudaFuncAttributeMaxDynamicSharedMemorySize,
                         smem_bytes);
    rnn_kernel<<<128, 256, smem_bytes>>>(Wh, out);

    const long long full =
        (long long)T_STEPS * BATCH * HDIM + (long long)BATCH * HDIM;
    if ((long long)out_size >= full)
        copy_hidden_kernel<<<(BATCH * HDIM) / 256, 256>>>(out);
}